// round 1
// baseline (speedup 1.0000x reference)
#include <cuda_runtime.h>
#include <cstdint>

#define NN 50000
#define EE 800000
#define HH 8
#define CC 32
#define HSZ 256
#define NEG_SLOPE 0.2f
#define EPSV 1e-16f

// ---------------- device scratch (static, no allocation) ----------------
__device__ float    g_xw[(size_t)NN * HSZ];     // x @ W            [N,256]  51.2MB
__device__ float    g_asrc[NN * HH];            // per-node src logits [N,8]
__device__ float    g_adst[NN * HH];            // per-node dst logits [N,8]
__device__ unsigned g_m[NN * HH];               // segment max (order-encoded uint)
__device__ float    g_denom[NN * HH];           // segment sum of exp
__device__ float    g_ev[(size_t)EE * HH];      // per-edge logits, then exp  25.6MB
__device__ int      g_is64;                     // edge_index dtype flag

// ---------------- helpers ----------------
__device__ __forceinline__ void red_add_v4(float* addr, float a, float b, float c, float d) {
    asm volatile("red.global.add.v4.f32 [%0], {%1,%2,%3,%4};"
                 :: "l"(addr), "f"(a), "f"(b), "f"(c), "f"(d) : "memory");
}

__device__ __forceinline__ void load_edge(const void* ei, int e, long long& s, long long& d) {
    if (g_is64) {
        const long long* p = (const long long*)ei;
        s = p[e]; d = p[EE + e];
    } else {
        const int* p = (const int*)ei;
        s = p[e]; d = p[EE + e];
    }
}

// ---------------- kernels ----------------

// Detect whether edge_index buffer is int64 (every odd 32-bit word == 0) or int32.
__global__ void k_detect(const unsigned* ei) {
    if (threadIdx.x == 0 && blockIdx.x == 0) {
        int all0 = 1;
        #pragma unroll 1
        for (int i = 0; i < 256; i++) all0 &= (ei[2 * i + 1] == 0u);
        g_is64 = all0;
    }
}

// Zero output accumulator, init segment max/denoms.
__global__ void k_init(float* __restrict__ out) {
    int stride = gridDim.x * blockDim.x;
    for (size_t i = blockIdx.x * blockDim.x + threadIdx.x; i < (size_t)NN * HSZ; i += stride)
        out[i] = 0.0f;
    for (int i = blockIdx.x * blockDim.x + threadIdx.x; i < NN * HH; i += stride) {
        g_m[i] = 0x007FFFFFu;   // order-encoding of -inf
        g_denom[i] = 0.0f;
    }
}

// Tiled fp32 GEMM: g_xw[N,256] = x[N,256] @ W[256,256]
#define BM 64
#define BN 64
#define BK 16
__global__ __launch_bounds__(256) void k_gemm(const float* __restrict__ A,
                                              const float* __restrict__ B) {
    __shared__ float As[BK][BM];
    __shared__ float Bs[BK][BN];
    int block_row = blockIdx.y * BM;
    int block_col = blockIdx.x * BN;
    int tid = threadIdx.x;
    int tr = tid / 16, tc = tid % 16;

    float acc[4][4] = {};
    for (int k0 = 0; k0 < HSZ; k0 += BK) {
        #pragma unroll
        for (int t = tid; t < BM * BK; t += 256) {
            int i = t / BK, j = t % BK;
            int row = block_row + i;
            As[j][i] = (row < NN) ? A[(size_t)row * HSZ + k0 + j] : 0.0f;
        }
        #pragma unroll
        for (int t = tid; t < BK * BN; t += 256) {
            int j = t / BN, c = t % BN;
            Bs[j][c] = B[(k0 + j) * HSZ + block_col + c];
        }
        __syncthreads();
        #pragma unroll
        for (int j = 0; j < BK; j++) {
            float4 av = *(const float4*)&As[j][tr * 4];
            float4 bv = *(const float4*)&Bs[j][tc * 4];
            float a[4] = {av.x, av.y, av.z, av.w};
            float b[4] = {bv.x, bv.y, bv.z, bv.w};
            #pragma unroll
            for (int i = 0; i < 4; i++)
                #pragma unroll
                for (int c = 0; c < 4; c++)
                    acc[i][c] += a[i] * b[c];
        }
        __syncthreads();
    }
    #pragma unroll
    for (int i = 0; i < 4; i++) {
        int row = block_row + tr * 4 + i;
        if (row < NN) {
            float4 v = make_float4(acc[i][0], acc[i][1], acc[i][2], acc[i][3]);
            *(float4*)&g_xw[(size_t)row * HSZ + block_col + tc * 4] = v;
        }
    }
}

// Per-(node,head) attention logits: a_src = <xw[n,h,:], att_src[h,:]>, same for dst
__global__ void k_att(const float* __restrict__ att_src, const float* __restrict__ att_dst) {
    int idx = blockIdx.x * blockDim.x + threadIdx.x;
    if (idx >= NN * HH) return;
    int n = idx >> 3, h = idx & 7;
    const float4* xp = (const float4*)(g_xw + (size_t)n * HSZ + h * CC);
    const float4* sp = (const float4*)(att_src + h * CC);
    const float4* dp = (const float4*)(att_dst + h * CC);
    float ss = 0.f, dd = 0.f;
    #pragma unroll
    for (int i = 0; i < 8; i++) {
        float4 v = xp[i], a = sp[i], b = dp[i];
        ss += v.x * a.x + v.y * a.y + v.z * a.z + v.w * a.w;
        dd += v.x * b.x + v.y * b.y + v.z * b.z + v.w * b.w;
    }
    g_asrc[idx] = ss;
    g_adst[idx] = dd;
}

// Edge pass 1: e = leaky_relu(a_src[src]+a_dst[dst]); store; atomicMax into segment max
__global__ void k_edge1(const void* __restrict__ ei) {
    int e = blockIdx.x * blockDim.x + threadIdx.x;
    if (e >= EE) return;
    long long s, d;
    load_edge(ei, e, s, d);
    const float4* ps = (const float4*)(g_asrc + s * HH);
    const float4* pd = (const float4*)(g_adst + d * HH);
    float4 s0 = ps[0], s1 = ps[1];
    float4 d0 = pd[0], d1 = pd[1];
    float v[8] = {s0.x + d0.x, s0.y + d0.y, s0.z + d0.z, s0.w + d0.w,
                  s1.x + d1.x, s1.y + d1.y, s1.z + d1.z, s1.w + d1.w};
    #pragma unroll
    for (int h = 0; h < 8; h++) {
        float f = v[h];
        f = (f > 0.f) ? f : NEG_SLOPE * f;
        v[h] = f;
        unsigned b = __float_as_uint(f);
        unsigned enc = (b & 0x80000000u) ? ~b : (b | 0x80000000u);
        atomicMax(&g_m[d * HH + h], enc);
    }
    float4* pe = (float4*)(g_ev + (size_t)e * HH);
    pe[0] = make_float4(v[0], v[1], v[2], v[3]);
    pe[1] = make_float4(v[4], v[5], v[6], v[7]);
}

// Edge pass 2: ex = exp(e - max[dst]); store; sum into denom
__global__ void k_edge2(const void* __restrict__ ei) {
    int e = blockIdx.x * blockDim.x + threadIdx.x;
    if (e >= EE) return;
    long long s, d;
    load_edge(ei, e, s, d);
    float4* pe = (float4*)(g_ev + (size_t)e * HH);
    float4 v0 = pe[0], v1 = pe[1];
    float v[8] = {v0.x, v0.y, v0.z, v0.w, v1.x, v1.y, v1.z, v1.w};
    float ex[8];
    #pragma unroll
    for (int h = 0; h < 8; h++) {
        unsigned u = g_m[d * HH + h];
        unsigned b = (u & 0x80000000u) ? (u & 0x7FFFFFFFu) : ~u;
        float mx = __uint_as_float(b);
        ex[h] = expf(v[h] - mx);
    }
    pe[0] = make_float4(ex[0], ex[1], ex[2], ex[3]);
    pe[1] = make_float4(ex[4], ex[5], ex[6], ex[7]);
    red_add_v4(&g_denom[d * HH], ex[0], ex[1], ex[2], ex[3]);
    red_add_v4(&g_denom[d * HH + 4], ex[4], ex[5], ex[6], ex[7]);
}

// Edge pass 3: one warp per edge. out[dst] += xw[src] * alpha
__global__ __launch_bounds__(256) void k_scatter(const void* __restrict__ ei,
                                                 float* __restrict__ out) {
    int warp = blockIdx.x * (blockDim.x >> 5) + (threadIdx.x >> 5);
    if (warp >= EE) return;
    int lane = threadIdx.x & 31;
    long long s, d;
    load_edge(ei, warp, s, d);
    int h = lane >> 2;  // lane covers channels [lane*8, lane*8+8) => head = lane/4
    float ex  = g_ev[(size_t)warp * HH + h];
    float den = g_denom[d * HH + h];
    float alpha = ex / (den + EPSV);
    const float4* xp = (const float4*)(g_xw + (size_t)s * HSZ + lane * 8);
    float4 a = xp[0], b = xp[1];
    float* op = out + (size_t)d * HSZ + lane * 8;
    red_add_v4(op,     a.x * alpha, a.y * alpha, a.z * alpha, a.w * alpha);
    red_add_v4(op + 4, b.x * alpha, b.y * alpha, b.z * alpha, b.w * alpha);
}

// Finalize: out = relu(out + bias)
__global__ void k_fin(float* __restrict__ out, const float* __restrict__ bias) {
    size_t idx = (size_t)blockIdx.x * blockDim.x + threadIdx.x;
    if (idx >= (size_t)NN * HSZ) return;
    float v = out[idx] + __ldg(&bias[idx & (HSZ - 1)]);
    out[idx] = v > 0.f ? v : 0.f;
}

// ---------------- launch ----------------
extern "C" void kernel_launch(void* const* d_in, const int* in_sizes, int n_in,
                              void* d_out, int out_size) {
    const float* x    = (const float*)d_in[0];
    const void*  ei   = d_in[1];
    const float* W    = (const float*)d_in[2];
    const float* asrc = (const float*)d_in[3];
    const float* adst = (const float*)d_in[4];
    const float* bias = (const float*)d_in[5];
    float* out = (float*)d_out;

    k_init<<<1024, 256>>>(out);
    k_detect<<<1, 32>>>((const unsigned*)ei);
    dim3 ggrid(HSZ / BN, (NN + BM - 1) / BM);
    k_gemm<<<ggrid, 256>>>(x, W);
    k_att<<<(NN * HH + 255) / 256, 256>>>(asrc, adst);
    k_edge1<<<(EE + 255) / 256, 256>>>(ei);
    k_edge2<<<(EE + 255) / 256, 256>>>(ei);
    k_scatter<<<(EE + 7) / 8, 256>>>(ei, out);
    k_fin<<<(NN * HSZ + 255) / 256, 256>>>(out, bias);
}

// round 2
// speedup vs baseline: 1.1328x; 1.1328x over previous
#include <cuda_runtime.h>
#include <cstdint>

#define NN 50000
#define EE 800000
#define HH 8
#define CC 32
#define HSZ 256
#define NEG_SLOPE 0.2f
#define EPSV 1e-16f

// ---------------- device scratch (static, no allocation) ----------------
__device__ float g_xw[(size_t)NN * HSZ];   // x @ W  [N,256]  51.2MB
__device__ float g_asrc[NN * HH];          // per-node src logits [N,8]
__device__ float g_adst[NN * HH];          // per-node dst logits [N,8]
__device__ float g_WS[HSZ * HH];           // W @ att_src-embed  [256,8]
__device__ float g_WD[HSZ * HH];           // W @ att_dst-embed  [256,8]
__device__ int   g_deg[NN];                // in-degree
__device__ int   g_off[NN + 1];            // CSR offsets
__device__ int   g_cur[NN];                // fill cursors
__device__ int   g_csr_src[EE];            // src node per CSR slot
__device__ int   g_is64;                   // edge_index dtype flag

// ---------------- helpers ----------------
__device__ __forceinline__ long long edge_dst(const void* ei, int e) {
    return g_is64 ? ((const long long*)ei)[EE + e] : (long long)((const int*)ei)[EE + e];
}
__device__ __forceinline__ void edge_sd(const void* ei, int e, long long& s, long long& d) {
    if (g_is64) { const long long* p = (const long long*)ei; s = p[e]; d = p[EE + e]; }
    else        { const int*       p = (const int*)ei;       s = p[e]; d = p[EE + e]; }
}

// ---------------- kernels ----------------

// Detect whether edge_index buffer is int64 (every odd 32-bit word == 0) or int32.
__global__ void k_detect(const unsigned* ei) {
    if (threadIdx.x == 0 && blockIdx.x == 0) {
        int all0 = 1;
        #pragma unroll 1
        for (int i = 0; i < 256; i++) all0 &= (ei[2 * i + 1] == 0u);
        g_is64 = all0;
    }
}

// Zero degree counters.
__global__ void k_zero() {
    int i = blockIdx.x * blockDim.x + threadIdx.x;
    if (i < NN) g_deg[i] = 0;
}

// WS[k][h] = sum_c W[k, h*32+c] * att_src[h,c]   (and WD for att_dst)
__global__ void k_ws(const float* __restrict__ W,
                     const float* __restrict__ att_src,
                     const float* __restrict__ att_dst) {
    int k = threadIdx.x;   // 256 threads, 1 block
    #pragma unroll
    for (int h = 0; h < HH; h++) {
        float ss = 0.f, dd = 0.f;
        #pragma unroll
        for (int c = 0; c < CC; c++) {
            float wv = W[(size_t)k * HSZ + h * CC + c];
            ss += wv * att_src[h * CC + c];
            dd += wv * att_dst[h * CC + c];
        }
        g_WS[k * HH + h] = ss;
        g_WD[k * HH + h] = dd;
    }
}

// Tiled fp32 GEMM: g_xw[N,256] = x[N,256] @ W[256,256]
// 128x128 tile, BK=16, 256 threads, 8x8 microtile.
#define BM 128
#define BN 128
#define BK 16
#define ASP 132   // padded leading dim for As (conflict-free transpose stores)
__global__ __launch_bounds__(256, 2) void k_gemm(const float* __restrict__ A,
                                                 const float* __restrict__ B) {
    __shared__ float As[BK][ASP];
    __shared__ float Bs[BK][BN];
    int brow = blockIdx.y * BM, bcol = blockIdx.x * BN;
    int tid = threadIdx.x;
    int tx = tid & 15, ty = tid >> 4;

    float acc[8][8] = {};
    for (int k0 = 0; k0 < HSZ; k0 += BK) {
        #pragma unroll
        for (int b = 0; b < 2; b++) {
            int v = tid + b * 256;          // 0..511 float4 slots
            int row = v >> 2, kq = v & 3;
            int gr = brow + row;
            float4 av = (gr < NN) ? *(const float4*)&A[(size_t)gr * HSZ + k0 + kq * 4]
                                  : make_float4(0.f, 0.f, 0.f, 0.f);
            As[kq * 4 + 0][row] = av.x;
            As[kq * 4 + 1][row] = av.y;
            As[kq * 4 + 2][row] = av.z;
            As[kq * 4 + 3][row] = av.w;
        }
        #pragma unroll
        for (int b = 0; b < 2; b++) {
            int v = tid + b * 256;
            int kr = v >> 5, c4 = v & 31;
            *(float4*)&Bs[kr][c4 * 4] =
                *(const float4*)&B[(size_t)(k0 + kr) * HSZ + bcol + c4 * 4];
        }
        __syncthreads();
        #pragma unroll
        for (int k = 0; k < BK; k++) {
            float4 a0 = *(float4*)&As[k][ty * 4];
            float4 a1 = *(float4*)&As[k][ty * 4 + 64];
            float4 b0 = *(float4*)&Bs[k][tx * 4];
            float4 b1 = *(float4*)&Bs[k][tx * 4 + 64];
            float ar[8] = {a0.x, a0.y, a0.z, a0.w, a1.x, a1.y, a1.z, a1.w};
            float br[8] = {b0.x, b0.y, b0.z, b0.w, b1.x, b1.y, b1.z, b1.w};
            #pragma unroll
            for (int i = 0; i < 8; i++)
                #pragma unroll
                for (int j = 0; j < 8; j++)
                    acc[i][j] += ar[i] * br[j];
        }
        __syncthreads();
    }
    #pragma unroll
    for (int i = 0; i < 8; i++) {
        int r = brow + ty * 4 + ((i < 4) ? i : 64 + i - 4);
        if (r < NN) {
            *(float4*)&g_xw[(size_t)r * HSZ + bcol + tx * 4] =
                make_float4(acc[i][0], acc[i][1], acc[i][2], acc[i][3]);
            *(float4*)&g_xw[(size_t)r * HSZ + bcol + tx * 4 + 64] =
                make_float4(acc[i][4], acc[i][5], acc[i][6], acc[i][7]);
        }
    }
}

// a_src/a_dst = x @ WS / x @ WD  — one warp per node.
__global__ __launch_bounds__(256) void k_att2(const float* __restrict__ x) {
    int w = blockIdx.x * (blockDim.x >> 5) + (threadIdx.x >> 5);
    if (w >= NN) return;
    int lane = threadIdx.x & 31;

    const float4* xp = (const float4*)(x + (size_t)w * HSZ + lane * 8);
    float4 x0 = xp[0], x1 = xp[1];
    float xr[8] = {x0.x, x0.y, x0.z, x0.w, x1.x, x1.y, x1.z, x1.w};

    float ps[8] = {}, pd[8] = {};
    #pragma unroll
    for (int kk = 0; kk < 8; kk++) {
        int k = lane * 8 + kk;
        float xv = xr[kk];
        float4 s0 = *(const float4*)&g_WS[k * HH];
        float4 s1 = *(const float4*)&g_WS[k * HH + 4];
        float4 d0 = *(const float4*)&g_WD[k * HH];
        float4 d1 = *(const float4*)&g_WD[k * HH + 4];
        ps[0] += xv * s0.x; ps[1] += xv * s0.y; ps[2] += xv * s0.z; ps[3] += xv * s0.w;
        ps[4] += xv * s1.x; ps[5] += xv * s1.y; ps[6] += xv * s1.z; ps[7] += xv * s1.w;
        pd[0] += xv * d0.x; pd[1] += xv * d0.y; pd[2] += xv * d0.z; pd[3] += xv * d0.w;
        pd[4] += xv * d1.x; pd[5] += xv * d1.y; pd[6] += xv * d1.z; pd[7] += xv * d1.w;
    }
    #pragma unroll
    for (int off = 16; off; off >>= 1) {
        #pragma unroll
        for (int h = 0; h < 8; h++) {
            ps[h] += __shfl_xor_sync(0xFFFFFFFFu, ps[h], off);
            pd[h] += __shfl_xor_sync(0xFFFFFFFFu, pd[h], off);
        }
    }
    if (lane < 8) {
        float v = 0.f;
        #pragma unroll
        for (int h = 0; h < 8; h++) if (h == lane) v = ps[h];
        g_asrc[(size_t)w * HH + lane] = v;
    } else if (lane < 16) {
        int l = lane - 8;
        float v = 0.f;
        #pragma unroll
        for (int h = 0; h < 8; h++) if (h == l) v = pd[h];
        g_adst[(size_t)w * HH + l] = v;
    }
}

// CSR build: count in-degrees.
__global__ void k_count(const void* __restrict__ ei) {
    int e = blockIdx.x * blockDim.x + threadIdx.x;
    if (e >= EE) return;
    atomicAdd(&g_deg[(int)edge_dst(ei, e)], 1);
}

// Exclusive prefix sum over g_deg -> g_off, g_cur. One block of 1024 threads.
__global__ void k_scan() {
    __shared__ int ssum[1024];
    const int CH = (NN + 1023) / 1024;   // 49
    int t = threadIdx.x;
    int base = t * CH;
    int s = 0;
    for (int i = 0; i < CH; i++) {
        int idx = base + i;
        if (idx < NN) s += g_deg[idx];
    }
    ssum[t] = s;
    __syncthreads();
    for (int off = 1; off < 1024; off <<= 1) {
        int v = (t >= off) ? ssum[t - off] : 0;
        __syncthreads();
        ssum[t] += v;
        __syncthreads();
    }
    int excl = (t == 0) ? 0 : ssum[t - 1];
    for (int i = 0; i < CH; i++) {
        int idx = base + i;
        if (idx < NN) {
            g_off[idx] = excl;
            g_cur[idx] = excl;
            excl += g_deg[idx];
        }
    }
    if (t == 1023) g_off[NN] = EE;
}

// CSR fill: slot per edge, record src.
__global__ void k_fill(const void* __restrict__ ei) {
    int e = blockIdx.x * blockDim.x + threadIdx.x;
    if (e >= EE) return;
    long long s, d;
    edge_sd(ei, e, s, d);
    int pos = atomicAdd(&g_cur[(int)d], 1);
    g_csr_src[pos] = (int)s;
}

// One warp per destination node: softmax over incoming edges + weighted
// aggregation + bias + relu, all in registers. No atomics.
__global__ __launch_bounds__(256) void k_aggregate(float* __restrict__ out,
                                                   const float* __restrict__ bias) {
    int n = blockIdx.x * (blockDim.x >> 5) + (threadIdx.x >> 5);
    if (n >= NN) return;
    int lane = threadIdx.x & 31;
    int h = lane >> 2;

    int beg = g_off[n], end = g_off[n + 1];
    float adn = g_adst[(size_t)n * HH + h];

    // pass 1: max logit for this head
    float m = -1e30f;
    int snext = (beg < end) ? g_csr_src[beg] : 0;
    for (int i = beg; i < end; i++) {
        int s = snext;
        if (i + 1 < end) snext = g_csr_src[i + 1];
        float e = g_asrc[(size_t)s * HH + h] + adn;
        e = (e > 0.f) ? e : NEG_SLOPE * e;
        m = fmaxf(m, e);
    }

    // pass 2: accumulate p and p * xw[src]
    float den = 0.f;
    float acc[8] = {};
    snext = (beg < end) ? g_csr_src[beg] : 0;
    for (int i = beg; i < end; i++) {
        int s = snext;
        if (i + 1 < end) snext = g_csr_src[i + 1];
        float e = g_asrc[(size_t)s * HH + h] + adn;
        e = (e > 0.f) ? e : NEG_SLOPE * e;
        float p = __expf(e - m);
        den += p;
        const float4* xp = (const float4*)(g_xw + (size_t)s * HSZ + lane * 8);
        float4 a = xp[0], b = xp[1];
        acc[0] += p * a.x; acc[1] += p * a.y; acc[2] += p * a.z; acc[3] += p * a.w;
        acc[4] += p * b.x; acc[5] += p * b.y; acc[6] += p * b.z; acc[7] += p * b.w;
    }

    float inv = 1.f / (den + EPSV);
    const float4* bp = (const float4*)(bias + lane * 8);
    float4 b0 = __ldg(bp), b1 = __ldg(bp + 1);
    float bb[8] = {b0.x, b0.y, b0.z, b0.w, b1.x, b1.y, b1.z, b1.w};
    float* op = out + (size_t)n * HSZ + lane * 8;
    float4 o0, o1;
    o0.x = fmaxf(acc[0] * inv + bb[0], 0.f);
    o0.y = fmaxf(acc[1] * inv + bb[1], 0.f);
    o0.z = fmaxf(acc[2] * inv + bb[2], 0.f);
    o0.w = fmaxf(acc[3] * inv + bb[3], 0.f);
    o1.x = fmaxf(acc[4] * inv + bb[4], 0.f);
    o1.y = fmaxf(acc[5] * inv + bb[5], 0.f);
    o1.z = fmaxf(acc[6] * inv + bb[6], 0.f);
    o1.w = fmaxf(acc[7] * inv + bb[7], 0.f);
    *(float4*)op = o0;
    *(float4*)(op + 4) = o1;
}

// ---------------- launch ----------------
extern "C" void kernel_launch(void* const* d_in, const int* in_sizes, int n_in,
                              void* d_out, int out_size) {
    const float* x    = (const float*)d_in[0];
    const void*  ei   = d_in[1];
    const float* W    = (const float*)d_in[2];
    const float* asrc = (const float*)d_in[3];
    const float* adst = (const float*)d_in[4];
    const float* bias = (const float*)d_in[5];
    float* out = (float*)d_out;

    k_detect<<<1, 32>>>((const unsigned*)ei);
    k_zero<<<(NN + 255) / 256, 256>>>();
    k_ws<<<1, 256>>>(W, asrc, adst);
    k_count<<<(EE + 255) / 256, 256>>>(ei);
    k_scan<<<1, 1024>>>();
    k_fill<<<(EE + 255) / 256, 256>>>(ei);
    dim3 ggrid(HSZ / BN, (NN + BM - 1) / BM);
    k_gemm<<<ggrid, 256>>>(x, W);
    k_att2<<<(NN * 32 + 255) / 256, 256>>>(x);
    k_aggregate<<<(NN * 32 + 255) / 256, 256>>>(out, bias);
}

// round 4
// speedup vs baseline: 1.2916x; 1.1401x over previous
#include <cuda_runtime.h>
#include <cuda_bf16.h>
#include <cstdint>

#define NN 50000
#define EE 800000
#define HH 8
#define CC 32
#define HSZ 256
#define NEG_SLOPE 0.2f
#define EPSV 1e-16f

// ---------------- device scratch (static, no allocation) ----------------
__device__ float g_xw[(size_t)NN * HSZ];   // x @ W  [N,256]  51.2MB
__device__ float g_asrc[NN * HH];
__device__ float g_adst[NN * HH];
__device__ float g_WS[HSZ * HH];
__device__ float g_WD[HSZ * HH];
__device__ __align__(16) __nv_bfloat16 g_xh[(size_t)NN * HSZ];  // x hi (bf16)
__device__ __align__(16) __nv_bfloat16 g_xl[(size_t)NN * HSZ];  // x lo (bf16)
__device__ __align__(16) __nv_bfloat16 g_wth[HSZ * HSZ];        // W^T hi [n][k]
__device__ __align__(16) __nv_bfloat16 g_wtl[HSZ * HSZ];        // W^T lo [n][k]
__device__ int   g_deg[NN];
__device__ int   g_off[NN + 1];
__device__ int   g_cur[NN];
__device__ int   g_csr_src[EE];
__device__ int   g_is64;

// ---------------- ptx helpers ----------------
__device__ __forceinline__ uint32_t smem_u32(const void* p) {
    uint32_t a;
    asm("{ .reg .u64 t; cvta.to.shared.u64 t, %1; cvt.u32.u64 %0, t; }" : "=r"(a) : "l"(p));
    return a;
}
__device__ __forceinline__ void ldsm_x4(uint32_t* r, uint32_t addr) {
    asm volatile("ldmatrix.sync.aligned.m8n8.x4.shared.b16 {%0,%1,%2,%3}, [%4];"
                 : "=r"(r[0]), "=r"(r[1]), "=r"(r[2]), "=r"(r[3]) : "r"(addr));
}
__device__ __forceinline__ void mma16816(float* c, const uint32_t* a, const uint32_t* b) {
    asm volatile("mma.sync.aligned.m16n8k16.row.col.f32.bf16.bf16.f32 "
                 "{%0,%1,%2,%3}, {%4,%5,%6,%7}, {%8,%9}, {%0,%1,%2,%3};"
                 : "+f"(c[0]), "+f"(c[1]), "+f"(c[2]), "+f"(c[3])
                 : "r"(a[0]), "r"(a[1]), "r"(a[2]), "r"(a[3]), "r"(b[0]), "r"(b[1]));
}

// ---------------- edge helpers ----------------
__device__ __forceinline__ long long edge_dst(const void* ei, int e) {
    return g_is64 ? ((const long long*)ei)[EE + e] : (long long)((const int*)ei)[EE + e];
}
__device__ __forceinline__ void edge_sd(const void* ei, int e, long long& s, long long& d) {
    if (g_is64) { const long long* p = (const long long*)ei; s = p[e]; d = p[EE + e]; }
    else        { const int*       p = (const int*)ei;       s = p[e]; d = p[EE + e]; }
}

// ---------------- small kernels ----------------
__global__ void k_detect(const unsigned* ei) {
    if (threadIdx.x == 0 && blockIdx.x == 0) {
        int all0 = 1;
        #pragma unroll 1
        for (int i = 0; i < 256; i++) all0 &= (ei[2 * i + 1] == 0u);
        g_is64 = all0;
    }
}
__global__ void k_zero() {
    int i = blockIdx.x * blockDim.x + threadIdx.x;
    if (i < NN) g_deg[i] = 0;
}
__global__ void k_ws(const float* __restrict__ W,
                     const float* __restrict__ att_src,
                     const float* __restrict__ att_dst) {
    int k = threadIdx.x;
    #pragma unroll
    for (int h = 0; h < HH; h++) {
        float ss = 0.f, dd = 0.f;
        #pragma unroll
        for (int c = 0; c < CC; c++) {
            float wv = W[(size_t)k * HSZ + h * CC + c];
            ss += wv * att_src[h * CC + c];
            dd += wv * att_dst[h * CC + c];
        }
        g_WS[k * HH + h] = ss;
        g_WD[k * HH + h] = dd;
    }
}
// W^T split into bf16 hi/lo: g_wth[n*256+k] = bf16(W[k][n]), lo = residual.
__global__ void k_wt(const float* __restrict__ W) {
    int i = blockIdx.x * blockDim.x + threadIdx.x;   // 65536
    int n = i >> 8, k = i & 255;
    float v = W[(size_t)k * HSZ + n];
    __nv_bfloat16 h = __float2bfloat16_rn(v);
    g_wth[i] = h;
    g_wtl[i] = __float2bfloat16_rn(v - __bfloat162float(h));
}
// x split into bf16 hi/lo (vectorized: 4 floats per thread).
__global__ void k_xsplit(const float* __restrict__ x) {
    size_t i = (size_t)blockIdx.x * blockDim.x + threadIdx.x;
    if (i >= (size_t)NN * HSZ / 4) return;
    float4 v = ((const float4*)x)[i];
    float f[4] = {v.x, v.y, v.z, v.w};
    __nv_bfloat16 h[4], l[4];
    #pragma unroll
    for (int j = 0; j < 4; j++) {
        h[j] = __float2bfloat16_rn(f[j]);
        l[j] = __float2bfloat16_rn(f[j] - __bfloat162float(h[j]));
    }
    __nv_bfloat162 h01 = __halves2bfloat162(h[0], h[1]);
    __nv_bfloat162 h23 = __halves2bfloat162(h[2], h[3]);
    __nv_bfloat162 l01 = __halves2bfloat162(l[0], l[1]);
    __nv_bfloat162 l23 = __halves2bfloat162(l[2], l[3]);
    ((uint2*)g_xh)[i] = make_uint2(*(uint32_t*)&h01, *(uint32_t*)&h23);
    ((uint2*)g_xl)[i] = make_uint2(*(uint32_t*)&l01, *(uint32_t*)&l23);
}
__global__ void k_count(const void* __restrict__ ei) {
    int e = blockIdx.x * blockDim.x + threadIdx.x;
    if (e >= EE) return;
    atomicAdd(&g_deg[(int)edge_dst(ei, e)], 1);
}
__global__ void k_scan() {
    __shared__ int ssum[1024];
    const int CH = (NN + 1023) / 1024;
    int t = threadIdx.x;
    int base = t * CH;
    int s = 0;
    for (int i = 0; i < CH; i++) { int idx = base + i; if (idx < NN) s += g_deg[idx]; }
    ssum[t] = s;
    __syncthreads();
    for (int off = 1; off < 1024; off <<= 1) {
        int v = (t >= off) ? ssum[t - off] : 0;
        __syncthreads();
        ssum[t] += v;
        __syncthreads();
    }
    int excl = (t == 0) ? 0 : ssum[t - 1];
    for (int i = 0; i < CH; i++) {
        int idx = base + i;
        if (idx < NN) { g_off[idx] = excl; g_cur[idx] = excl; excl += g_deg[idx]; }
    }
    if (t == 1023) g_off[NN] = EE;
}
__global__ void k_fill(const void* __restrict__ ei) {
    int e = blockIdx.x * blockDim.x + threadIdx.x;
    if (e >= EE) return;
    long long s, d;
    edge_sd(ei, e, s, d);
    int pos = atomicAdd(&g_cur[(int)d], 1);
    g_csr_src[pos] = (int)s;
}

// ---------------- mma.sync GEMM: g_xw = x @ W (bf16 split-3, fp32 accum) ----------------
// CTA tile 128(M) x 128(N), K in 4 chunks of 64. 8 warps: 4(M) x 2(N), warp tile 32x64.
#define PITCHB 144                 // bytes per SMEM row (72 bf16)
#define SA_HI 0
#define SA_LO (128 * PITCHB)       // 18432
#define SB_HI (2 * 128 * PITCHB)   // 36864
#define SB_LO (3 * 128 * PITCHB)   // 55296
#define SMEMTOT (4 * 128 * PITCHB) // 73728

__global__ __launch_bounds__(256, 2) void k_gemm_mma() {
    extern __shared__ char smem[];
    uint32_t sb = smem_u32(smem);
    int tid = threadIdx.x;
    int wid = tid >> 5, lane = tid & 31;
    int brow = blockIdx.y * 128;
    int bcol = blockIdx.x * 128;
    int mbase = (wid & 3) * 32;    // warp M offset within tile
    int nbase = (wid >> 2) * 64;   // warp N offset within tile

    float acc[2][8][4];
    #pragma unroll
    for (int mt = 0; mt < 2; mt++)
        #pragma unroll
        for (int nt = 0; nt < 8; nt++)
            #pragma unroll
            for (int j = 0; j < 4; j++) acc[mt][nt][j] = 0.f;

    for (int kc = 0; kc < 4; kc++) {
        int k0 = kc * 64;
        // load A tiles (hi+lo): 128 rows x 64 cols bf16
        #pragma unroll
        for (int v = 0; v < 4; v++) {
            int g = tid + v * 256;
            int r = g >> 3, sl = g & 7;
            int gr = brow + r;
            uint4 h, l;
            if (gr < NN) {
                size_t src = (size_t)gr * HSZ + k0 + sl * 8;
                h = *(const uint4*)&g_xh[src];
                l = *(const uint4*)&g_xl[src];
            } else {
                h = make_uint4(0, 0, 0, 0);
                l = h;
            }
            *(uint4*)(smem + SA_HI + r * PITCHB + sl * 16) = h;
            *(uint4*)(smem + SA_LO + r * PITCHB + sl * 16) = l;
        }
        // load B tiles (hi+lo): 128 n-rows x 64 k-cols bf16
        #pragma unroll
        for (int v = 0; v < 4; v++) {
            int g = tid + v * 256;
            int r = g >> 3, sl = g & 7;
            size_t src = (size_t)(bcol + r) * HSZ + k0 + sl * 8;
            *(uint4*)(smem + SB_HI + r * PITCHB + sl * 16) = *(const uint4*)&g_wth[src];
            *(uint4*)(smem + SB_LO + r * PITCHB + sl * 16) = *(const uint4*)&g_wtl[src];
        }
        __syncthreads();

        #pragma unroll
        for (int ks = 0; ks < 4; ks++) {
            uint32_t ah[2][4], al[2][4];
            #pragma unroll
            for (int mt = 0; mt < 2; mt++) {
                uint32_t r = mbase + mt * 16 + (lane & 15);
                uint32_t c = ks * 16 + ((lane >> 4) << 3);
                uint32_t off = r * PITCHB + c * 2;
                ldsm_x4(ah[mt], sb + SA_HI + off);
                ldsm_x4(al[mt], sb + SA_LO + off);
            }
            #pragma unroll
            for (int ntg = 0; ntg < 4; ntg++) {
                uint32_t rn = nbase + ntg * 16 + (lane & 7) + (((lane >> 4) & 1) << 3);
                uint32_t ck = ks * 16 + (((lane >> 3) & 1) << 3);
                uint32_t boff = rn * PITCHB + ck * 2;
                uint32_t bh[4], bl[4];
                ldsm_x4(bh, sb + SB_HI + boff);
                ldsm_x4(bl, sb + SB_LO + boff);
                #pragma unroll
                for (int mt = 0; mt < 2; mt++) {
                    #pragma unroll
                    for (int half = 0; half < 2; half++) {
                        float* c = acc[mt][ntg * 2 + half];
                        mma16816(c, ah[mt], &bh[half * 2]);
                        mma16816(c, al[mt], &bh[half * 2]);
                        mma16816(c, ah[mt], &bl[half * 2]);
                    }
                }
            }
        }
        __syncthreads();
    }

    // epilogue: c-frag lane mapping -> g_xw
    #pragma unroll
    for (int mt = 0; mt < 2; mt++) {
        int r0 = brow + mbase + mt * 16 + (lane >> 2);
        #pragma unroll
        for (int nt = 0; nt < 8; nt++) {
            int cc = bcol + nbase + nt * 8 + (lane & 3) * 2;
            if (r0 < NN)
                *(float2*)&g_xw[(size_t)r0 * HSZ + cc] =
                    make_float2(acc[mt][nt][0], acc[mt][nt][1]);
            if (r0 + 8 < NN)
                *(float2*)&g_xw[(size_t)(r0 + 8) * HSZ + cc] =
                    make_float2(acc[mt][nt][2], acc[mt][nt][3]);
        }
    }
}

// ---------------- attention logits: a_src/a_dst = x @ WS / WD ----------------
__global__ __launch_bounds__(256) void k_att2(const float* __restrict__ x) {
    int w = blockIdx.x * (blockDim.x >> 5) + (threadIdx.x >> 5);
    if (w >= NN) return;
    int lane = threadIdx.x & 31;

    const float4* xp = (const float4*)(x + (size_t)w * HSZ + lane * 8);
    float4 x0 = xp[0], x1 = xp[1];
    float xr[8] = {x0.x, x0.y, x0.z, x0.w, x1.x, x1.y, x1.z, x1.w};

    float ps[8] = {}, pd[8] = {};
    #pragma unroll
    for (int kk = 0; kk < 8; kk++) {
        int k = lane * 8 + kk;
        float xv = xr[kk];
        float4 s0 = *(const float4*)&g_WS[k * HH];
        float4 s1 = *(const float4*)&g_WS[k * HH + 4];
        float4 d0 = *(const float4*)&g_WD[k * HH];
        float4 d1 = *(const float4*)&g_WD[k * HH + 4];
        ps[0] += xv * s0.x; ps[1] += xv * s0.y; ps[2] += xv * s0.z; ps[3] += xv * s0.w;
        ps[4] += xv * s1.x; ps[5] += xv * s1.y; ps[6] += xv * s1.z; ps[7] += xv * s1.w;
        pd[0] += xv * d0.x; pd[1] += xv * d0.y; pd[2] += xv * d0.z; pd[3] += xv * d0.w;
        pd[4] += xv * d1.x; pd[5] += xv * d1.y; pd[6] += xv * d1.z; pd[7] += xv * d1.w;
    }
    #pragma unroll
    for (int off = 16; off; off >>= 1) {
        #pragma unroll
        for (int h = 0; h < 8; h++) {
            ps[h] += __shfl_xor_sync(0xFFFFFFFFu, ps[h], off);
            pd[h] += __shfl_xor_sync(0xFFFFFFFFu, pd[h], off);
        }
    }
    if (lane < 8) {
        float v = 0.f;
        #pragma unroll
        for (int h = 0; h < 8; h++) if (h == lane) v = ps[h];
        g_asrc[(size_t)w * HH + lane] = v;
    } else if (lane < 16) {
        int l = lane - 8;
        float v = 0.f;
        #pragma unroll
        for (int h = 0; h < 8; h++) if (h == l) v = pd[h];
        g_adst[(size_t)w * HH + l] = v;
    }
}

// ---------------- per-dst softmax + aggregation (warp per node) ----------------
__global__ __launch_bounds__(256) void k_aggregate(float* __restrict__ out,
                                                   const float* __restrict__ bias) {
    int n = blockIdx.x * (blockDim.x >> 5) + (threadIdx.x >> 5);
    if (n >= NN) return;
    int lane = threadIdx.x & 31;
    int h = lane >> 2;

    int beg = g_off[n], end = g_off[n + 1];
    float adn = g_adst[(size_t)n * HH + h];

    float m = -1e30f;
    int snext = (beg < end) ? g_csr_src[beg] : 0;
    for (int i = beg; i < end; i++) {
        int s = snext;
        if (i + 1 < end) snext = g_csr_src[i + 1];
        float e = g_asrc[(size_t)s * HH + h] + adn;
        e = (e > 0.f) ? e : NEG_SLOPE * e;
        m = fmaxf(m, e);
    }

    float den = 0.f;
    float acc[8] = {};
    snext = (beg < end) ? g_csr_src[beg] : 0;
    for (int i = beg; i < end; i++) {
        int s = snext;
        if (i + 1 < end) snext = g_csr_src[i + 1];
        float e = g_asrc[(size_t)s * HH + h] + adn;
        e = (e > 0.f) ? e : NEG_SLOPE * e;
        float p = __expf(e - m);
        den += p;
        const float4* xp = (const float4*)(g_xw + (size_t)s * HSZ + lane * 8);
        float4 a = xp[0], b = xp[1];
        acc[0] += p * a.x; acc[1] += p * a.y; acc[2] += p * a.z; acc[3] += p * a.w;
        acc[4] += p * b.x; acc[5] += p * b.y; acc[6] += p * b.z; acc[7] += p * b.w;
    }

    float inv = 1.f / (den + EPSV);
    const float4* bp = (const float4*)(bias + lane * 8);
    float4 b0 = __ldg(bp), b1 = __ldg(bp + 1);
    float bb[8] = {b0.x, b0.y, b0.z, b0.w, b1.x, b1.y, b1.z, b1.w};
    float* op = out + (size_t)n * HSZ + lane * 8;
    float4 o0, o1;
    o0.x = fmaxf(acc[0] * inv + bb[0], 0.f);
    o0.y = fmaxf(acc[1] * inv + bb[1], 0.f);
    o0.z = fmaxf(acc[2] * inv + bb[2], 0.f);
    o0.w = fmaxf(acc[3] * inv + bb[3], 0.f);
    o1.x = fmaxf(acc[4] * inv + bb[4], 0.f);
    o1.y = fmaxf(acc[5] * inv + bb[5], 0.f);
    o1.z = fmaxf(acc[6] * inv + bb[6], 0.f);
    o1.w = fmaxf(acc[7] * inv + bb[7], 0.f);
    *(float4*)op = o0;
    *(float4*)(op + 4) = o1;
}

// ---------------- launch ----------------
extern "C" void kernel_launch(void* const* d_in, const int* in_sizes, int n_in,
                              void* d_out, int out_size) {
    const float* x    = (const float*)d_in[0];
    const void*  ei   = d_in[1];
    const float* W    = (const float*)d_in[2];
    const float* asrc = (const float*)d_in[3];
    const float* adst = (const float*)d_in[4];
    const float* bias = (const float*)d_in[5];
    float* out = (float*)d_out;

    cudaFuncSetAttribute(k_gemm_mma, cudaFuncAttributeMaxDynamicSharedMemorySize, SMEMTOT);

    k_detect<<<1, 32>>>((const unsigned*)ei);
    k_zero<<<(NN + 255) / 256, 256>>>();
    k_ws<<<1, 256>>>(W, asrc, adst);
    k_wt<<<HSZ * HSZ / 256, 256>>>(W);
    k_xsplit<<<(NN * HSZ / 4 + 255) / 256, 256>>>(x);
    k_count<<<(EE + 255) / 256, 256>>>(ei);
    k_scan<<<1, 1024>>>();
    k_fill<<<(EE + 255) / 256, 256>>>(ei);
    dim3 ggrid(2, (NN + 127) / 128);
    k_gemm_mma<<<ggrid, 256, SMEMTOT>>>();
    k_att2<<<(NN * 32 + 255) / 256, 256>>>(x);
    k_aggregate<<<(NN * 32 + 255) / 256, 256>>>(out, bias);
}

// round 5
// speedup vs baseline: 2.5277x; 1.9570x over previous
#include <cuda_runtime.h>
#include <cuda_bf16.h>
#include <cstdint>

#define NN 50000
#define EE 800000
#define HH 8
#define CC 32
#define HSZ 256
#define NEG_SLOPE 0.2f
#define EPSV 1e-16f

// ---------------- device scratch (static, no allocation) ----------------
__device__ float g_xw[(size_t)NN * HSZ];   // x @ W  [N,256]  51.2MB
__device__ float g_asrc[NN * HH];
__device__ float g_adst[NN * HH];
__device__ __align__(16) __nv_bfloat16 g_wth[HSZ * HSZ];  // W^T hi [n][k]
__device__ __align__(16) __nv_bfloat16 g_wtl[HSZ * HSZ];  // W^T lo [n][k]
__device__ int   g_deg[NN];
__device__ int   g_off[NN + 1];
__device__ int   g_cur[NN];
__device__ int   g_csr_src[EE];
__device__ int   g_is64;

// ---------------- ptx helpers ----------------
__device__ __forceinline__ uint32_t smem_u32(const void* p) {
    uint32_t a;
    asm("{ .reg .u64 t; cvta.to.shared.u64 t, %1; cvt.u32.u64 %0, t; }" : "=r"(a) : "l"(p));
    return a;
}
__device__ __forceinline__ void ldsm_x4(uint32_t* r, uint32_t addr) {
    asm volatile("ldmatrix.sync.aligned.m8n8.x4.shared.b16 {%0,%1,%2,%3}, [%4];"
                 : "=r"(r[0]), "=r"(r[1]), "=r"(r[2]), "=r"(r[3]) : "r"(addr));
}
__device__ __forceinline__ void mma16816(float* c, const uint32_t* a, const uint32_t* b) {
    asm volatile("mma.sync.aligned.m16n8k16.row.col.f32.bf16.bf16.f32 "
                 "{%0,%1,%2,%3}, {%4,%5,%6,%7}, {%8,%9}, {%0,%1,%2,%3};"
                 : "+f"(c[0]), "+f"(c[1]), "+f"(c[2]), "+f"(c[3])
                 : "r"(a[0]), "r"(a[1]), "r"(a[2]), "r"(a[3]), "r"(b[0]), "r"(b[1]));
}

// ---------------- edge helpers ----------------
__device__ __forceinline__ long long edge_dst(const void* ei, int e) {
    return g_is64 ? ((const long long*)ei)[EE + e] : (long long)((const int*)ei)[EE + e];
}
__device__ __forceinline__ void edge_sd(const void* ei, int e, long long& s, long long& d) {
    if (g_is64) { const long long* p = (const long long*)ei; s = p[e]; d = p[EE + e]; }
    else        { const int*       p = (const int*)ei;       s = p[e]; d = p[EE + e]; }
}

// ---------------- prep: detect dtype + zero degrees + split W^T ----------------
__global__ void k_prep(const unsigned* __restrict__ ei, const float* __restrict__ W) {
    int i = blockIdx.x * blockDim.x + threadIdx.x;   // 65536
    if (i == 0) {
        int all0 = 1;
        #pragma unroll 1
        for (int j = 0; j < 256; j++) all0 &= (ei[2 * j + 1] == 0u);
        g_is64 = all0;
    }
    if (i < NN) g_deg[i] = 0;
    {
        int n = i >> 8, k = i & 255;
        float v = W[(size_t)k * HSZ + n];
        __nv_bfloat16 h = __float2bfloat16_rn(v);
        g_wth[i] = h;
        g_wtl[i] = __float2bfloat16_rn(v - __bfloat162float(h));
    }
}

// ---------------- CSR build ----------------
__global__ void k_count(const void* __restrict__ ei) {
    int e = blockIdx.x * blockDim.x + threadIdx.x;
    if (e >= EE) return;
    atomicAdd(&g_deg[(int)edge_dst(ei, e)], 1);
}
__global__ void k_scan() {
    __shared__ int ssum[1024];
    const int CH = (NN + 1023) / 1024;
    int t = threadIdx.x;
    int base = t * CH;
    int s = 0;
    for (int i = 0; i < CH; i++) { int idx = base + i; if (idx < NN) s += g_deg[idx]; }
    ssum[t] = s;
    __syncthreads();
    for (int off = 1; off < 1024; off <<= 1) {
        int v = (t >= off) ? ssum[t - off] : 0;
        __syncthreads();
        ssum[t] += v;
        __syncthreads();
    }
    int excl = (t == 0) ? 0 : ssum[t - 1];
    for (int i = 0; i < CH; i++) {
        int idx = base + i;
        if (idx < NN) { g_off[idx] = excl; g_cur[idx] = excl; excl += g_deg[idx]; }
    }
    if (t == 1023) g_off[NN] = EE;
}
__global__ void k_fill(const void* __restrict__ ei) {
    int e = blockIdx.x * blockDim.x + threadIdx.x;
    if (e >= EE) return;
    long long s, d;
    edge_sd(ei, e, s, d);
    int pos = atomicAdd(&g_cur[(int)d], 1);
    g_csr_src[pos] = (int)s;
}

// ---------------- fused GEMM + attention logits ----------------
// CTA tile: M=64 rows x N=256 (full width), K in 4 chunks of 64.
// 256 threads = 8 warps: 2(M) x 4(N); warp tile 32x64 (= exactly 2 heads wide).
// bf16 split-3 (hi*hi + lo*hi + hi*lo), fp32 accum.
// Epilogue writes g_xw AND computes a_src/a_dst from resident fragments.
#define PITCHB 144                 // bytes per SMEM row (72 bf16)
#define SA_HI 0                    // 64 x 144 = 9216
#define SA_LO 9216
#define SB_HI 18432                // 256 x 144 = 36864
#define SB_LO 55296
#define SMEMTOT 92160

__global__ __launch_bounds__(256, 2) void k_gemm_mma(const float* __restrict__ x,
                                                     const float* __restrict__ att_src,
                                                     const float* __restrict__ att_dst) {
    extern __shared__ char smem[];
    uint32_t sb = smem_u32(smem);
    int tid = threadIdx.x;
    int wid = tid >> 5, lane = tid & 31;
    int brow = blockIdx.x * 64;
    int mbase = (wid & 1) * 32;    // warp M offset
    int nwarp = wid >> 1;
    int nbase = nwarp * 64;        // warp N offset (2 heads)

    float acc[2][8][4];
    #pragma unroll
    for (int mt = 0; mt < 2; mt++)
        #pragma unroll
        for (int nt = 0; nt < 8; nt++)
            #pragma unroll
            for (int j = 0; j < 4; j++) acc[mt][nt][j] = 0.f;

    for (int kc = 0; kc < 4; kc++) {
        int k0 = kc * 64;
        // A: x[brow..brow+63, k0..k0+63] fp32 -> bf16 hi/lo in SMEM
        #pragma unroll
        for (int v = 0; v < 4; v++) {
            int g = tid + v * 256;           // 1024 float4 slots
            int r = g >> 4, fq = g & 15;
            int gr = brow + r;
            float4 vv = (gr < NN) ? *(const float4*)&x[(size_t)gr * HSZ + k0 + fq * 4]
                                  : make_float4(0.f, 0.f, 0.f, 0.f);
            __nv_bfloat16 h0 = __float2bfloat16_rn(vv.x), h1 = __float2bfloat16_rn(vv.y);
            __nv_bfloat16 h2 = __float2bfloat16_rn(vv.z), h3 = __float2bfloat16_rn(vv.w);
            __nv_bfloat16 l0 = __float2bfloat16_rn(vv.x - __bfloat162float(h0));
            __nv_bfloat16 l1 = __float2bfloat16_rn(vv.y - __bfloat162float(h1));
            __nv_bfloat16 l2 = __float2bfloat16_rn(vv.z - __bfloat162float(h2));
            __nv_bfloat16 l3 = __float2bfloat16_rn(vv.w - __bfloat162float(h3));
            __nv_bfloat162 ph0 = __halves2bfloat162(h0, h1), ph1 = __halves2bfloat162(h2, h3);
            __nv_bfloat162 pl0 = __halves2bfloat162(l0, l1), pl1 = __halves2bfloat162(l2, l3);
            *(uint2*)(smem + SA_HI + r * PITCHB + fq * 8) =
                make_uint2(*(uint32_t*)&ph0, *(uint32_t*)&ph1);
            *(uint2*)(smem + SA_LO + r * PITCHB + fq * 8) =
                make_uint2(*(uint32_t*)&pl0, *(uint32_t*)&pl1);
        }
        // B: W^T[n=0..255, k0..k0+63] hi/lo (pre-split bf16)
        #pragma unroll
        for (int v = 0; v < 8; v++) {
            int g = tid + v * 256;           // 2048 uint4 slots
            int n = g >> 3, sl = g & 7;
            size_t src = (size_t)n * HSZ + k0 + sl * 8;
            *(uint4*)(smem + SB_HI + n * PITCHB + sl * 16) = *(const uint4*)&g_wth[src];
            *(uint4*)(smem + SB_LO + n * PITCHB + sl * 16) = *(const uint4*)&g_wtl[src];
        }
        __syncthreads();

        #pragma unroll
        for (int ks = 0; ks < 4; ks++) {
            uint32_t ah[2][4], al[2][4];
            #pragma unroll
            for (int mt = 0; mt < 2; mt++) {
                uint32_t r = mbase + mt * 16 + (lane & 15);
                uint32_t c = ks * 16 + ((lane >> 4) << 3);
                uint32_t off = r * PITCHB + c * 2;
                ldsm_x4(ah[mt], sb + SA_HI + off);
                ldsm_x4(al[mt], sb + SA_LO + off);
            }
            #pragma unroll
            for (int ntg = 0; ntg < 4; ntg++) {
                uint32_t rn = nbase + ntg * 16 + (lane & 7) + (((lane >> 4) & 1) << 3);
                uint32_t ck = ks * 16 + (((lane >> 3) & 1) << 3);
                uint32_t boff = rn * PITCHB + ck * 2;
                uint32_t bh[4], bl[4];
                ldsm_x4(bh, sb + SB_HI + boff);
                ldsm_x4(bl, sb + SB_LO + boff);
                #pragma unroll
                for (int mt = 0; mt < 2; mt++) {
                    #pragma unroll
                    for (int half = 0; half < 2; half++) {
                        float* c = acc[mt][ntg * 2 + half];
                        mma16816(c, ah[mt], &bh[half * 2]);
                        mma16816(c, al[mt], &bh[half * 2]);
                        mma16816(c, ah[mt], &bl[half * 2]);
                    }
                }
            }
        }
        __syncthreads();
    }

    // ---- epilogue 1: write xw ----
    #pragma unroll
    for (int mt = 0; mt < 2; mt++) {
        int r0 = brow + mbase + mt * 16 + (lane >> 2);
        #pragma unroll
        for (int nt = 0; nt < 8; nt++) {
            int cc = nbase + nt * 8 + (lane & 3) * 2;
            if (r0 < NN)
                *(float2*)&g_xw[(size_t)r0 * HSZ + cc] =
                    make_float2(acc[mt][nt][0], acc[mt][nt][1]);
            if (r0 + 8 < NN)
                *(float2*)&g_xw[(size_t)(r0 + 8) * HSZ + cc] =
                    make_float2(acc[mt][nt][2], acc[mt][nt][3]);
        }
    }

    // ---- epilogue 2: attention logits from fragments ----
    float* att_s = (float*)smem;         // reuse SMEM (all MMAs done)
    float* att_d = (float*)smem + 256;
    if (tid < 256) { att_s[tid] = att_src[tid]; att_d[tid] = att_dst[tid]; }
    __syncthreads();

    float ds[2][2][2] = {}, dd2[2][2][2] = {};
    #pragma unroll
    for (int mt = 0; mt < 2; mt++)
        #pragma unroll
        for (int nt = 0; nt < 8; nt++) {
            int hh = nt >> 2;
            int colb = nbase + nt * 8 + (lane & 3) * 2;
            #pragma unroll
            for (int j = 0; j < 4; j++) {
                int col = colb + (j & 1);
                float v = acc[mt][nt][j];
                ds[mt][j >> 1][hh]  += v * att_s[col];
                dd2[mt][j >> 1][hh] += v * att_d[col];
            }
        }
    #pragma unroll
    for (int off = 1; off <= 2; off <<= 1) {
        #pragma unroll
        for (int mt = 0; mt < 2; mt++)
            #pragma unroll
            for (int rs = 0; rs < 2; rs++)
                #pragma unroll
                for (int hh = 0; hh < 2; hh++) {
                    ds[mt][rs][hh]  += __shfl_xor_sync(0xFFFFFFFFu, ds[mt][rs][hh], off);
                    dd2[mt][rs][hh] += __shfl_xor_sync(0xFFFFFFFFu, dd2[mt][rs][hh], off);
                }
    }
    if ((lane & 3) == 0) {
        int hb = nwarp * 2;
        #pragma unroll
        for (int mt = 0; mt < 2; mt++)
            #pragma unroll
            for (int rs = 0; rs < 2; rs++) {
                int row = brow + mbase + mt * 16 + (lane >> 2) + rs * 8;
                if (row < NN) {
                    #pragma unroll
                    for (int hh = 0; hh < 2; hh++) {
                        g_asrc[(size_t)row * HH + hb + hh] = ds[mt][rs][hh];
                        g_adst[(size_t)row * HH + hb + hh] = dd2[mt][rs][hh];
                    }
                }
            }
    }
}

// ---------------- single-pass per-dst softmax + aggregation ----------------
__global__ __launch_bounds__(256) void k_aggregate(float* __restrict__ out,
                                                   const float* __restrict__ bias) {
    int n = blockIdx.x * (blockDim.x >> 5) + (threadIdx.x >> 5);
    if (n >= NN) return;
    int lane = threadIdx.x & 31;
    int h = lane >> 2;

    int beg = g_off[n], end = g_off[n + 1];
    float adn = g_adst[(size_t)n * HH + h];

    float den = 0.f;
    float acc[8] = {};
    int i = beg;
    #pragma unroll 1
    for (; i + 2 <= end; i += 2) {
        int s0 = __ldg(&g_csr_src[i]);
        int s1 = __ldg(&g_csr_src[i + 1]);
        float e0 = g_asrc[(size_t)s0 * HH + h] + adn;
        float e1 = g_asrc[(size_t)s1 * HH + h] + adn;
        e0 = (e0 > 0.f) ? e0 : NEG_SLOPE * e0;
        e1 = (e1 > 0.f) ? e1 : NEG_SLOPE * e1;
        const float4* x0 = (const float4*)(g_xw + (size_t)s0 * HSZ + lane * 8);
        const float4* x1 = (const float4*)(g_xw + (size_t)s1 * HSZ + lane * 8);
        float4 a0 = x0[0], b0 = x0[1];
        float4 a1 = x1[0], b1 = x1[1];
        float p0 = __expf(e0), p1 = __expf(e1);
        den += p0 + p1;
        acc[0] += p0 * a0.x + p1 * a1.x;
        acc[1] += p0 * a0.y + p1 * a1.y;
        acc[2] += p0 * a0.z + p1 * a1.z;
        acc[3] += p0 * a0.w + p1 * a1.w;
        acc[4] += p0 * b0.x + p1 * b1.x;
        acc[5] += p0 * b0.y + p1 * b1.y;
        acc[6] += p0 * b0.z + p1 * b1.z;
        acc[7] += p0 * b0.w + p1 * b1.w;
    }
    if (i < end) {
        int s0 = __ldg(&g_csr_src[i]);
        float e0 = g_asrc[(size_t)s0 * HH + h] + adn;
        e0 = (e0 > 0.f) ? e0 : NEG_SLOPE * e0;
        const float4* x0 = (const float4*)(g_xw + (size_t)s0 * HSZ + lane * 8);
        float4 a0 = x0[0], b0 = x0[1];
        float p0 = __expf(e0);
        den += p0;
        acc[0] += p0 * a0.x; acc[1] += p0 * a0.y; acc[2] += p0 * a0.z; acc[3] += p0 * a0.w;
        acc[4] += p0 * b0.x; acc[5] += p0 * b0.y; acc[6] += p0 * b0.z; acc[7] += p0 * b0.w;
    }

    float inv = 1.f / (den + EPSV);
    const float4* bp = (const float4*)(bias + lane * 8);
    float4 b0 = __ldg(bp), b1 = __ldg(bp + 1);
    float* op = out + (size_t)n * HSZ + lane * 8;
    float4 o0, o1;
    o0.x = fmaxf(acc[0] * inv + b0.x, 0.f);
    o0.y = fmaxf(acc[1] * inv + b0.y, 0.f);
    o0.z = fmaxf(acc[2] * inv + b0.z, 0.f);
    o0.w = fmaxf(acc[3] * inv + b0.w, 0.f);
    o1.x = fmaxf(acc[4] * inv + b1.x, 0.f);
    o1.y = fmaxf(acc[5] * inv + b1.y, 0.f);
    o1.z = fmaxf(acc[6] * inv + b1.z, 0.f);
    o1.w = fmaxf(acc[7] * inv + b1.w, 0.f);
    *(float4*)op = o0;
    *(float4*)(op + 4) = o1;
}

// ---------------- launch ----------------
extern "C" void kernel_launch(void* const* d_in, const int* in_sizes, int n_in,
                              void* d_out, int out_size) {
    const float* x    = (const float*)d_in[0];
    const void*  ei   = d_in[1];
    const float* W    = (const float*)d_in[2];
    const float* asrc = (const float*)d_in[3];
    const float* adst = (const float*)d_in[4];
    const float* bias = (const float*)d_in[5];
    float* out = (float*)d_out;

    cudaFuncSetAttribute(k_gemm_mma, cudaFuncAttributeMaxDynamicSharedMemorySize, SMEMTOT);

    k_prep<<<256, 256>>>((const unsigned*)ei, W);
    k_count<<<(EE + 255) / 256, 256>>>(ei);
    k_scan<<<1, 1024>>>();
    k_fill<<<(EE + 255) / 256, 256>>>(ei);
    k_gemm_mma<<<(NN + 63) / 64, 256, SMEMTOT>>>(x, asrc, adst);
    k_aggregate<<<(NN * 32 + 255) / 256, 256>>>(out, bias);
}

// round 6
// speedup vs baseline: 2.8595x; 1.1313x over previous
#include <cuda_runtime.h>
#include <cuda_bf16.h>
#include <cuda_fp16.h>
#include <cstdint>

#define NN 50000
#define EE 800000
#define HH 8
#define CC 32
#define HSZ 256
#define NEG_SLOPE 0.2f
#define EPSV 1e-16f

// ---------------- device scratch (static, no allocation) ----------------
__device__ __align__(16) __half g_xwh[(size_t)NN * HSZ];  // x @ W in fp16  25.6MB
__device__ float g_asrc[NN * HH];
__device__ float g_adst[NN * HH];
__device__ __align__(16) __nv_bfloat16 g_wth[HSZ * HSZ];  // W^T hi [n][k]
__device__ __align__(16) __nv_bfloat16 g_wtl[HSZ * HSZ];  // W^T lo [n][k]
__device__ int   g_deg[NN];
__device__ int   g_off[NN + 1];
__device__ int   g_cur[NN];
__device__ int   g_csr_src[EE];
__device__ int   g_is64;

// ---------------- ptx helpers ----------------
__device__ __forceinline__ uint32_t smem_u32(const void* p) {
    uint32_t a;
    asm("{ .reg .u64 t; cvta.to.shared.u64 t, %1; cvt.u32.u64 %0, t; }" : "=r"(a) : "l"(p));
    return a;
}
__device__ __forceinline__ void ldsm_x4(uint32_t* r, uint32_t addr) {
    asm volatile("ldmatrix.sync.aligned.m8n8.x4.shared.b16 {%0,%1,%2,%3}, [%4];"
                 : "=r"(r[0]), "=r"(r[1]), "=r"(r[2]), "=r"(r[3]) : "r"(addr));
}
__device__ __forceinline__ void mma16816(float* c, const uint32_t* a, const uint32_t* b) {
    asm volatile("mma.sync.aligned.m16n8k16.row.col.f32.bf16.bf16.f32 "
                 "{%0,%1,%2,%3}, {%4,%5,%6,%7}, {%8,%9}, {%0,%1,%2,%3};"
                 : "+f"(c[0]), "+f"(c[1]), "+f"(c[2]), "+f"(c[3])
                 : "r"(a[0]), "r"(a[1]), "r"(a[2]), "r"(a[3]), "r"(b[0]), "r"(b[1]));
}

// ---------------- edge helpers ----------------
__device__ __forceinline__ long long edge_dst(const void* ei, int e) {
    return g_is64 ? ((const long long*)ei)[EE + e] : (long long)((const int*)ei)[EE + e];
}
__device__ __forceinline__ void edge_sd(const void* ei, int e, long long& s, long long& d) {
    if (g_is64) { const long long* p = (const long long*)ei; s = p[e]; d = p[EE + e]; }
    else        { const int*       p = (const int*)ei;       s = p[e]; d = p[EE + e]; }
}

// ---------------- side-stream chain: detect + zero + CSR build ----------------
__global__ void k_zero(const unsigned* __restrict__ ei) {
    int i = blockIdx.x * blockDim.x + threadIdx.x;
    if (i == 0) {
        int all0 = 1;
        #pragma unroll 1
        for (int j = 0; j < 256; j++) all0 &= (ei[2 * j + 1] == 0u);
        g_is64 = all0;
    }
    if (i < NN) g_deg[i] = 0;
}
__global__ void k_count(const void* __restrict__ ei) {
    int e = blockIdx.x * blockDim.x + threadIdx.x;
    if (e >= EE) return;
    atomicAdd(&g_deg[(int)edge_dst(ei, e)], 1);
}
__global__ void k_scan() {
    __shared__ int ssum[1024];
    const int CH = (NN + 1023) / 1024;
    int t = threadIdx.x;
    int base = t * CH;
    int s = 0;
    for (int i = 0; i < CH; i++) { int idx = base + i; if (idx < NN) s += g_deg[idx]; }
    ssum[t] = s;
    __syncthreads();
    for (int off = 1; off < 1024; off <<= 1) {
        int v = (t >= off) ? ssum[t - off] : 0;
        __syncthreads();
        ssum[t] += v;
        __syncthreads();
    }
    int excl = (t == 0) ? 0 : ssum[t - 1];
    for (int i = 0; i < CH; i++) {
        int idx = base + i;
        if (idx < NN) { g_off[idx] = excl; g_cur[idx] = excl; excl += g_deg[idx]; }
    }
    if (t == 1023) g_off[NN] = EE;
}
__global__ void k_fill(const void* __restrict__ ei) {
    int e = blockIdx.x * blockDim.x + threadIdx.x;
    if (e >= EE) return;
    long long s, d;
    edge_sd(ei, e, s, d);
    int pos = atomicAdd(&g_cur[(int)d], 1);
    g_csr_src[pos] = (int)s;
}

// ---------------- main-stream prep: split W^T into bf16 hi/lo ----------------
__global__ void k_prep_w(const float* __restrict__ W) {
    int i = blockIdx.x * blockDim.x + threadIdx.x;   // 65536
    int n = i >> 8, k = i & 255;
    float v = W[(size_t)k * HSZ + n];
    __nv_bfloat16 h = __float2bfloat16_rn(v);
    g_wth[i] = h;
    g_wtl[i] = __float2bfloat16_rn(v - __bfloat162float(h));
}

// ---------------- fused GEMM + attention logits ----------------
// CTA tile: M=64 x N=256 (full width), K in 4 chunks of 64.
// 256 threads = 8 warps: 2(M) x 4(N); warp tile 32x64 (= exactly 2 heads).
// bf16 split-3 (hi*hi + lo*hi + hi*lo), fp32 accum -> fp16 xw + fp32 logits.
#define PITCHB 144
#define SA_HI 0
#define SA_LO 9216
#define SB_HI 18432
#define SB_LO 55296
#define SMEMTOT 92160

__global__ __launch_bounds__(256, 2) void k_gemm_mma(const float* __restrict__ x,
                                                     const float* __restrict__ att_src,
                                                     const float* __restrict__ att_dst) {
    extern __shared__ char smem[];
    uint32_t sb = smem_u32(smem);
    int tid = threadIdx.x;
    int wid = tid >> 5, lane = tid & 31;
    int brow = blockIdx.x * 64;
    int mbase = (wid & 1) * 32;
    int nwarp = wid >> 1;
    int nbase = nwarp * 64;

    float acc[2][8][4];
    #pragma unroll
    for (int mt = 0; mt < 2; mt++)
        #pragma unroll
        for (int nt = 0; nt < 8; nt++)
            #pragma unroll
            for (int j = 0; j < 4; j++) acc[mt][nt][j] = 0.f;

    for (int kc = 0; kc < 4; kc++) {
        int k0 = kc * 64;
        // A: x[brow..brow+63, k0..k0+63] fp32 -> bf16 hi/lo
        #pragma unroll
        for (int v = 0; v < 4; v++) {
            int g = tid + v * 256;
            int r = g >> 4, fq = g & 15;
            int gr = brow + r;
            float4 vv = (gr < NN) ? *(const float4*)&x[(size_t)gr * HSZ + k0 + fq * 4]
                                  : make_float4(0.f, 0.f, 0.f, 0.f);
            __nv_bfloat16 h0 = __float2bfloat16_rn(vv.x), h1 = __float2bfloat16_rn(vv.y);
            __nv_bfloat16 h2 = __float2bfloat16_rn(vv.z), h3 = __float2bfloat16_rn(vv.w);
            __nv_bfloat16 l0 = __float2bfloat16_rn(vv.x - __bfloat162float(h0));
            __nv_bfloat16 l1 = __float2bfloat16_rn(vv.y - __bfloat162float(h1));
            __nv_bfloat16 l2 = __float2bfloat16_rn(vv.z - __bfloat162float(h2));
            __nv_bfloat16 l3 = __float2bfloat16_rn(vv.w - __bfloat162float(h3));
            __nv_bfloat162 ph0 = __halves2bfloat162(h0, h1), ph1 = __halves2bfloat162(h2, h3);
            __nv_bfloat162 pl0 = __halves2bfloat162(l0, l1), pl1 = __halves2bfloat162(l2, l3);
            *(uint2*)(smem + SA_HI + r * PITCHB + fq * 8) =
                make_uint2(*(uint32_t*)&ph0, *(uint32_t*)&ph1);
            *(uint2*)(smem + SA_LO + r * PITCHB + fq * 8) =
                make_uint2(*(uint32_t*)&pl0, *(uint32_t*)&pl1);
        }
        // B: W^T hi/lo
        #pragma unroll
        for (int v = 0; v < 8; v++) {
            int g = tid + v * 256;
            int n = g >> 3, sl = g & 7;
            size_t src = (size_t)n * HSZ + k0 + sl * 8;
            *(uint4*)(smem + SB_HI + n * PITCHB + sl * 16) = *(const uint4*)&g_wth[src];
            *(uint4*)(smem + SB_LO + n * PITCHB + sl * 16) = *(const uint4*)&g_wtl[src];
        }
        __syncthreads();

        #pragma unroll
        for (int ks = 0; ks < 4; ks++) {
            uint32_t ah[2][4], al[2][4];
            #pragma unroll
            for (int mt = 0; mt < 2; mt++) {
                uint32_t r = mbase + mt * 16 + (lane & 15);
                uint32_t c = ks * 16 + ((lane >> 4) << 3);
                uint32_t off = r * PITCHB + c * 2;
                ldsm_x4(ah[mt], sb + SA_HI + off);
                ldsm_x4(al[mt], sb + SA_LO + off);
            }
            #pragma unroll
            for (int ntg = 0; ntg < 4; ntg++) {
                uint32_t rn = nbase + ntg * 16 + (lane & 7) + (((lane >> 4) & 1) << 3);
                uint32_t ck = ks * 16 + (((lane >> 3) & 1) << 3);
                uint32_t boff = rn * PITCHB + ck * 2;
                uint32_t bh[4], bl[4];
                ldsm_x4(bh, sb + SB_HI + boff);
                ldsm_x4(bl, sb + SB_LO + boff);
                #pragma unroll
                for (int mt = 0; mt < 2; mt++) {
                    #pragma unroll
                    for (int half = 0; half < 2; half++) {
                        float* c = acc[mt][ntg * 2 + half];
                        mma16816(c, ah[mt], &bh[half * 2]);
                        mma16816(c, al[mt], &bh[half * 2]);
                        mma16816(c, ah[mt], &bl[half * 2]);
                    }
                }
            }
        }
        __syncthreads();
    }

    // ---- epilogue 1: write xw as fp16 ----
    #pragma unroll
    for (int mt = 0; mt < 2; mt++) {
        int r0 = brow + mbase + mt * 16 + (lane >> 2);
        #pragma unroll
        for (int nt = 0; nt < 8; nt++) {
            int cc = nbase + nt * 8 + (lane & 3) * 2;
            if (r0 < NN) {
                __half2 p = __floats2half2_rn(acc[mt][nt][0], acc[mt][nt][1]);
                *(uint32_t*)&g_xwh[(size_t)r0 * HSZ + cc] = *(uint32_t*)&p;
            }
            if (r0 + 8 < NN) {
                __half2 p = __floats2half2_rn(acc[mt][nt][2], acc[mt][nt][3]);
                *(uint32_t*)&g_xwh[(size_t)(r0 + 8) * HSZ + cc] = *(uint32_t*)&p;
            }
        }
    }

    // ---- epilogue 2: attention logits from fragments ----
    float* att_s = (float*)smem;
    float* att_d = (float*)smem + 256;
    if (tid < 256) { att_s[tid] = att_src[tid]; att_d[tid] = att_dst[tid]; }
    __syncthreads();

    float ds[2][2][2] = {}, dd2[2][2][2] = {};
    #pragma unroll
    for (int mt = 0; mt < 2; mt++)
        #pragma unroll
        for (int nt = 0; nt < 8; nt++) {
            int hh = nt >> 2;
            int colb = nbase + nt * 8 + (lane & 3) * 2;
            #pragma unroll
            for (int j = 0; j < 4; j++) {
                int col = colb + (j & 1);
                float v = acc[mt][nt][j];
                ds[mt][j >> 1][hh]  += v * att_s[col];
                dd2[mt][j >> 1][hh] += v * att_d[col];
            }
        }
    #pragma unroll
    for (int off = 1; off <= 2; off <<= 1) {
        #pragma unroll
        for (int mt = 0; mt < 2; mt++)
            #pragma unroll
            for (int rs = 0; rs < 2; rs++)
                #pragma unroll
                for (int hh = 0; hh < 2; hh++) {
                    ds[mt][rs][hh]  += __shfl_xor_sync(0xFFFFFFFFu, ds[mt][rs][hh], off);
                    dd2[mt][rs][hh] += __shfl_xor_sync(0xFFFFFFFFu, dd2[mt][rs][hh], off);
                }
    }
    if ((lane & 3) == 0) {
        int hb = nwarp * 2;
        #pragma unroll
        for (int mt = 0; mt < 2; mt++)
            #pragma unroll
            for (int rs = 0; rs < 2; rs++) {
                int row = brow + mbase + mt * 16 + (lane >> 2) + rs * 8;
                if (row < NN) {
                    #pragma unroll
                    for (int hh = 0; hh < 2; hh++) {
                        g_asrc[(size_t)row * HH + hb + hh] = ds[mt][rs][hh];
                        g_adst[(size_t)row * HH + hb + hh] = dd2[mt][rs][hh];
                    }
                }
            }
    }
}

// ---------------- single-pass per-dst softmax + aggregation (fp16 gather) ----------------
__device__ __forceinline__ void acc_row(float* acc, const uint4 q, float p) {
    float2 f0 = __half22float2(*(const __half2*)&q.x);
    float2 f1 = __half22float2(*(const __half2*)&q.y);
    float2 f2 = __half22float2(*(const __half2*)&q.z);
    float2 f3 = __half22float2(*(const __half2*)&q.w);
    acc[0] += p * f0.x; acc[1] += p * f0.y;
    acc[2] += p * f1.x; acc[3] += p * f1.y;
    acc[4] += p * f2.x; acc[5] += p * f2.y;
    acc[6] += p * f3.x; acc[7] += p * f3.y;
}

__global__ __launch_bounds__(256) void k_aggregate(float* __restrict__ out,
                                                   const float* __restrict__ bias) {
    int n = blockIdx.x * (blockDim.x >> 5) + (threadIdx.x >> 5);
    if (n >= NN) return;
    int lane = threadIdx.x & 31;
    int h = lane >> 2;

    int beg = g_off[n], end = g_off[n + 1];
    float adn = g_adst[(size_t)n * HH + h];

    float den = 0.f;
    float acc[8] = {};
    int i = beg;
    #pragma unroll 1
    for (; i + 2 <= end; i += 2) {
        int s0 = __ldg(&g_csr_src[i]);
        int s1 = __ldg(&g_csr_src[i + 1]);
        float e0 = g_asrc[(size_t)s0 * HH + h] + adn;
        float e1 = g_asrc[(size_t)s1 * HH + h] + adn;
        e0 = (e0 > 0.f) ? e0 : NEG_SLOPE * e0;
        e1 = (e1 > 0.f) ? e1 : NEG_SLOPE * e1;
        uint4 q0 = *(const uint4*)(g_xwh + (size_t)s0 * HSZ + lane * 8);
        uint4 q1 = *(const uint4*)(g_xwh + (size_t)s1 * HSZ + lane * 8);
        float p0 = __expf(e0), p1 = __expf(e1);
        den += p0 + p1;
        acc_row(acc, q0, p0);
        acc_row(acc, q1, p1);
    }
    if (i < end) {
        int s0 = __ldg(&g_csr_src[i]);
        float e0 = g_asrc[(size_t)s0 * HH + h] + adn;
        e0 = (e0 > 0.f) ? e0 : NEG_SLOPE * e0;
        uint4 q0 = *(const uint4*)(g_xwh + (size_t)s0 * HSZ + lane * 8);
        float p0 = __expf(e0);
        den += p0;
        acc_row(acc, q0, p0);
    }

    float inv = 1.f / (den + EPSV);
    const float4* bp = (const float4*)(bias + lane * 8);
    float4 b0 = __ldg(bp), b1 = __ldg(bp + 1);
    float* op = out + (size_t)n * HSZ + lane * 8;
    float4 o0, o1;
    o0.x = fmaxf(acc[0] * inv + b0.x, 0.f);
    o0.y = fmaxf(acc[1] * inv + b0.y, 0.f);
    o0.z = fmaxf(acc[2] * inv + b0.z, 0.f);
    o0.w = fmaxf(acc[3] * inv + b0.w, 0.f);
    o1.x = fmaxf(acc[4] * inv + b1.x, 0.f);
    o1.y = fmaxf(acc[5] * inv + b1.y, 0.f);
    o1.z = fmaxf(acc[6] * inv + b1.z, 0.f);
    o1.w = fmaxf(acc[7] * inv + b1.w, 0.f);
    *(float4*)op = o0;
    *(float4*)(op + 4) = o1;
}

// ---------------- launch ----------------
extern "C" void kernel_launch(void* const* d_in, const int* in_sizes, int n_in,
                              void* d_out, int out_size) {
    const float* x    = (const float*)d_in[0];
    const void*  ei   = d_in[1];
    const float* W    = (const float*)d_in[2];
    const float* asrc = (const float*)d_in[3];
    const float* adst = (const float*)d_in[4];
    const float* bias = (const float*)d_in[5];
    float* out = (float*)d_out;

    cudaFuncSetAttribute(k_gemm_mma, cudaFuncAttributeMaxDynamicSharedMemorySize, SMEMTOT);

    // Fork CSR build onto a side stream so it overlaps the GEMM.
    cudaStream_t s1;
    cudaStreamCreateWithFlags(&s1, cudaStreamNonBlocking);
    cudaEvent_t e0, e1;
    cudaEventCreateWithFlags(&e0, cudaEventDisableTiming);
    cudaEventCreateWithFlags(&e1, cudaEventDisableTiming);

    cudaEventRecord(e0, 0);
    cudaStreamWaitEvent(s1, e0, 0);
    k_zero<<<(NN + 255) / 256, 256, 0, s1>>>((const unsigned*)ei);
    k_count<<<(EE + 255) / 256, 256, 0, s1>>>(ei);
    k_scan<<<1, 1024, 0, s1>>>();
    k_fill<<<(EE + 255) / 256, 256, 0, s1>>>(ei);
    cudaEventRecord(e1, s1);

    k_prep_w<<<256, 256>>>(W);
    k_gemm_mma<<<(NN + 63) / 64, 256, SMEMTOT>>>(x, asrc, adst);

    cudaStreamWaitEvent(0, e1, 0);
    k_aggregate<<<(NN * 32 + 255) / 256, 256>>>(out, bias);

    cudaEventDestroy(e0);
    cudaEventDestroy(e1);
    cudaStreamDestroy(s1);
}